// round 9
// baseline (speedup 1.0000x reference)
#include <cuda_runtime.h>
#include <cstdint>

// DetectionLayer: x (16, 255, 76, 76) f32 -> out (16, 17328, 85) f32
// out[b, a*5776 + gy*76 + gx, c]:
//   c==0: (sigmoid(x0)+gx)*8 ; c==1: (sigmoid(x1)+gy)*8
//   c==2: exp(x2)*aw[a]      ; c==3: exp(x3)*ah[a]
//   c>=4: sigmoid(xc)
// sigmoid(v) = 0.5 + 0.5*tanh(v/2) (1 MUFU).
// Block = (b, a, 4 gy rows). Two half-tiles, each TMA-bulk-stored async so the
// first store overlaps the second half's compute. Phase-1 loop prefetches the
// next float4 before transforming the current one.

#define NG     76
#define NGG    (NG * NG)          // 5776
#define NGG4   (NGG / 4)          // 1444 float4 per channel plane
#define NA     3
#define NCH    85
#define NROWS  4                  // gy rows per block
#define HROWS  2                  // gy rows per half
#define HV4    (HROWS * NG / 4)   // 38 float4s per channel per half
#define NV4H   (NCH * HV4)        // 3230 float4 items per half
#define HALF_F (HROWS * NG * NCH) // 12920 floats per half
#define HALF_B (HALF_F * 4)       // 51680 bytes per half
#define TILE_B (2 * HALF_B)       // 103360 bytes
#define NTHR   1024

__device__ __forceinline__ float tanh_half(float v) {
    float t;
    asm("tanh.approx.f32 %0, %1;" : "=f"(t) : "f"(v * 0.5f));
    return t;  // tanh(v/2); sigmoid(v) = fmaf(t, 0.5f, 0.5f)
}

// Process one half (h = 0/1): items v = c*38 + qh, q = h*38 + qh in [0,76).
// Writes tile[(gy_off*76 + gx)*85 + c] for gy_off = q/19 in [0,4).
__device__ __forceinline__ void process_half(
    int h, const float4* __restrict__ src4, float* __restrict__ tile,
    float aw, float ah, int gy0, int tid)
{
    int v = tid;
    int c  = v / HV4;
    int qh = v - c * HV4;

    // prologue load
    float4 cur;
    if (v < NV4H) cur = src4[c * NGG4 + h * HV4 + qh];

    #pragma unroll 1
    while (v < NV4H) {
        // next indices + prefetch (v += 1024 => c += 26, qh += 36; 1024=26*38+36)
        int vn = v + NTHR;
        int cn = c + 26, qhn = qh + 36;
        if (qhn >= HV4) { qhn -= HV4; ++cn; }
        float4 nxt;
        if (vn < NV4H) nxt = src4[cn * NGG4 + h * HV4 + qhn];

        // transform current
        const int q      = h * HV4 + qh;
        const int gy_off = q / 19;
        const int gx0    = (q - gy_off * 19) << 2;

        float o0, o1, o2, o3;
        if (c >= 4) {
            o0 = fmaf(tanh_half(cur.x), 0.5f, 0.5f);
            o1 = fmaf(tanh_half(cur.y), 0.5f, 0.5f);
            o2 = fmaf(tanh_half(cur.z), 0.5f, 0.5f);
            o3 = fmaf(tanh_half(cur.w), 0.5f, 0.5f);
        } else if (c == 0) {
            const float base = fmaf((float)gx0, 8.0f, 4.0f);
            o0 = fmaf(tanh_half(cur.x), 4.0f, base);
            o1 = fmaf(tanh_half(cur.y), 4.0f, base + 8.0f);
            o2 = fmaf(tanh_half(cur.z), 4.0f, base + 16.0f);
            o3 = fmaf(tanh_half(cur.w), 4.0f, base + 24.0f);
        } else if (c == 1) {
            const float base = fmaf((float)(gy0 + gy_off), 8.0f, 4.0f);
            o0 = fmaf(tanh_half(cur.x), 4.0f, base);
            o1 = fmaf(tanh_half(cur.y), 4.0f, base);
            o2 = fmaf(tanh_half(cur.z), 4.0f, base);
            o3 = fmaf(tanh_half(cur.w), 4.0f, base);
        } else {
            const float an = (c == 2) ? aw : ah;
            o0 = __expf(cur.x) * an; o1 = __expf(cur.y) * an;
            o2 = __expf(cur.z) * an; o3 = __expf(cur.w) * an;
        }
        float* t = &tile[(gy_off * NG + gx0) * NCH + c];
        t[0]       = o0;
        t[NCH]     = o1;
        t[2 * NCH] = o2;
        t[3 * NCH] = o3;

        v = vn; c = cn; qh = qhn; cur = nxt;
    }
}

__global__ __launch_bounds__(NTHR)
void detection_layer_kernel(const float* __restrict__ x, float* __restrict__ out) {
    extern __shared__ __align__(16) float tile[];  // TILE_B bytes, final layout

    const int tid = threadIdx.x;
    const int gy0 = blockIdx.x * NROWS;  // 0,4,..,72
    const int a   = blockIdx.y;          // 0..2
    const int b   = blockIdx.z;          // 0..15

    const float aw = (a == 0) ? 10.0f : (a == 1 ? 16.0f : 33.0f);
    const float ah = (a == 0) ? 13.0f : (a == 1 ? 30.0f : 23.0f);

    // input base for (b, a*85 + 0, gy0, 0); 16B-aligned (gy0 mult of 4)
    const float4* src4 = reinterpret_cast<const float4*>(
        x + ((size_t)(b * (NA * NCH) + a * NCH) * NG + gy0) * NG);

    float* dst = out + ((size_t)b * (NA * NGG) + a * NGG + gy0 * NG) * (size_t)NCH;

    uint32_t saddr;
    asm("{ .reg .u64 t; cvta.to.shared.u64 t, %1; cvt.u32.u64 %0, t; }"
        : "=r"(saddr) : "l"(tile));

    // ---- half 0: compute, then async TMA store (no wait) ----
    process_half(0, src4, tile, aw, ah, gy0, tid);
    __syncthreads();
    if (tid == 0) {
        asm volatile("fence.proxy.async.shared::cta;" ::: "memory");
        asm volatile(
            "cp.async.bulk.global.shared::cta.bulk_group [%0], [%1], %2;"
            :: "l"(dst), "r"(saddr), "r"((uint32_t)HALF_B) : "memory");
        asm volatile("cp.async.bulk.commit_group;" ::: "memory");
    }

    // ---- half 1: compute overlaps half-0 store drain ----
    process_half(1, src4, tile, aw, ah, gy0, tid);
    __syncthreads();
    if (tid == 0) {
        asm volatile("fence.proxy.async.shared::cta;" ::: "memory");
        asm volatile(
            "cp.async.bulk.global.shared::cta.bulk_group [%0], [%1], %2;"
            :: "l"(dst + HALF_F), "r"(saddr + (uint32_t)HALF_B),
               "r"((uint32_t)HALF_B) : "memory");
        asm volatile("cp.async.bulk.commit_group;" ::: "memory");
        // keep CTA (and its smem) alive until the engine has read both halves
        asm volatile("cp.async.bulk.wait_group.read 0;" ::: "memory");
    }
}

extern "C" void kernel_launch(void* const* d_in, const int* in_sizes, int n_in,
                              void* d_out, int out_size) {
    const float* x = (const float*)d_in[0];
    float* out = (float*)d_out;

    static bool attr_set = false;
    if (!attr_set) {
        cudaFuncSetAttribute(detection_layer_kernel,
                             cudaFuncAttributeMaxDynamicSharedMemorySize,
                             TILE_B);
        attr_set = true;
    }

    dim3 grid(NG / NROWS, NA, 16);
    detection_layer_kernel<<<grid, NTHR, TILE_B>>>(x, out);
}

// round 10
// speedup vs baseline: 1.0985x; 1.0985x over previous
#include <cuda_runtime.h>
#include <cstdint>

// DetectionLayer: x (16, 255, 76, 76) f32 -> out (16, 17328, 85) f32
// Fully engine-driven pipeline:
//   TMA bulk g2s loads (85 x 304B per row, mbarrier) -> smem input buffer
//   warps: conflict-free smem->smem transform (sigmoid/exp/affine)
//   TMA bulk s2g store (25840B per row, bulk_group)
// Double-buffered over 4 gy rows per block.

#define NG     76
#define NGG    (NG * NG)      // 5776
#define NA     3
#define NCH    85
#define NROWS  4              // gy rows per block
#define ROW_F  (NG * NCH)     // 6460 floats (output row chunk)
#define ROW_B  (ROW_F * 4)    // 25840 bytes (= input row: 85 ch x 304B)
#define SEG_B  (NG * 4)       // 304 bytes per channel segment
#define NCG    21             // channel quads (84) + tail channel 84
#define NITEM  (NCG * NG)     // 1596 quad items per row
#define NTHR   512

// dynamic smem layout (floats):
//   in[0]  @ 0        (6460 floats, channel-major: c*76 + s)
//   in[1]  @ 6460
//   out[0] @ 12920    (final layout: s*85 + c)
//   out[1] @ 19380
#define IN_OFF(buf)  ((buf) * ROW_F)
#define OUT_OFF(buf) ((2 + (buf)) * ROW_F)
#define SMEM_B (4 * ROW_B)

__device__ __forceinline__ float tanh_half(float v) {
    float t;
    asm("tanh.approx.f32 %0, %1;" : "=f"(t) : "f"(v * 0.5f));
    return t;  // tanh(v/2); sigmoid(v) = fmaf(t, 0.5f, 0.5f)
}

__global__ __launch_bounds__(NTHR)
void detection_layer_kernel(const float* __restrict__ x, float* __restrict__ out) {
    extern __shared__ __align__(16) float smem[];
    __shared__ __align__(8) uint64_t mbar[2];

    const int tid = threadIdx.x;
    const int gy0 = blockIdx.x * NROWS;  // 0,4,..,72
    const int a   = blockIdx.y;          // 0..2
    const int b   = blockIdx.z;          // 0..15

    const float aw = (a == 0) ? 10.0f : (a == 1 ? 16.0f : 33.0f);
    const float ah = (a == 0) ? 13.0f : (a == 1 ? 30.0f : 23.0f);

    // global input base for (b, a*85, gy0, 0) in bytes
    const char* srcb = (const char*)x +
        ((size_t)(b * (NA * NCH) + a * NCH) * NGG + (size_t)gy0 * NG) * 4;
    // global output base
    float* dst = out + ((size_t)b * (NA * NGG) + a * NGG + (size_t)gy0 * NG) * NCH;

    uint32_t sbase;
    asm("{ .reg .u64 t; cvta.to.shared.u64 t, %1; cvt.u32.u64 %0, t; }"
        : "=r"(sbase) : "l"(smem));
    uint32_t mbase;
    asm("{ .reg .u64 t; cvta.to.shared.u64 t, %1; cvt.u32.u64 %0, t; }"
        : "=r"(mbase) : "l"(mbar));

    // ---- init mbarriers, prologue expect_tx for rows 0,1 ----
    if (tid == 0) {
        asm volatile("mbarrier.init.shared.b64 [%0], 1;" :: "r"(mbase)     : "memory");
        asm volatile("mbarrier.init.shared.b64 [%0], 1;" :: "r"(mbase + 8) : "memory");
        asm volatile("fence.proxy.async.shared::cta;" ::: "memory");
        asm volatile("mbarrier.arrive.expect_tx.shared.b64 _, [%0], %1;"
                     :: "r"(mbase), "r"((uint32_t)ROW_B) : "memory");
        asm volatile("mbarrier.arrive.expect_tx.shared.b64 _, [%0], %1;"
                     :: "r"(mbase + 8), "r"((uint32_t)ROW_B) : "memory");
    }
    __syncthreads();

    // ---- prologue loads: rows 0 and 1, one 304B bulk copy per channel ----
    if (tid < NCH) {
        const uint64_t g0 = (uint64_t)(srcb + (size_t)tid * (NGG * 4));
        #pragma unroll
        for (int rb = 0; rb < 2; ++rb) {
            asm volatile(
                "cp.async.bulk.shared::cluster.global.mbarrier::complete_tx::bytes "
                "[%0], [%1], %2, [%3];"
                :: "r"(sbase + (uint32_t)(IN_OFF(rb) * 4) + (uint32_t)(tid * SEG_B)),
                   "l"(g0 + (uint32_t)(rb * SEG_B)),
                   "r"((uint32_t)SEG_B),
                   "r"(mbase + rb * 8)
                : "memory");
        }
    }

    // ---- pipeline over rows ----
    #pragma unroll 1
    for (int r = 0; r < NROWS; ++r) {
        const int buf = r & 1;
        const uint32_t mb = mbase + buf * 8;
        const uint32_t ph = (uint32_t)(r >> 1) & 1u;

        // wait input row ready
        {
            uint32_t done;
            asm volatile(
                "{ .reg .pred p; mbarrier.try_wait.parity.shared.b64 p, [%1], %2; "
                "selp.b32 %0, 1, 0, p; }"
                : "=r"(done) : "r"(mb), "r"(ph) : "memory");
            while (!done) {
                asm volatile(
                    "{ .reg .pred p; mbarrier.try_wait.parity.shared.b64 p, [%1], %2, 0x989680; "
                    "selp.b32 %0, 1, 0, p; }"
                    : "=r"(done) : "r"(mb), "r"(ph) : "memory");
            }
        }

        if (tid == 0) {
            if (r >= 2) {  // out[buf] must be drained before rewrite
                asm volatile("cp.async.bulk.wait_group.read 1;" ::: "memory");
            }
            if (r + 2 < NROWS) {  // expect next fill of in[buf] (next phase)
                asm volatile("mbarrier.arrive.expect_tx.shared.b64 _, [%0], %1;"
                             :: "r"(mb), "r"((uint32_t)ROW_B) : "memory");
            }
        }
        __syncthreads();

        // ---- compute: in[buf] (c*76+s) -> out[buf] (s*85+c), conflict-free ----
        {
            const float* __restrict__ ib = smem + IN_OFF(buf);
            float* __restrict__ ob = smem + OUT_OFF(buf);
            const float ybase = fmaf((float)(gy0 + r), 8.0f, 4.0f);

            int i  = tid;
            int cg = tid / NG;
            int s  = tid - cg * NG;
            #pragma unroll 1
            for (; i < NITEM; i += NTHR) {
                const float* p = ib + (cg << 2) * NG + s;
                const float v0 = p[0];
                const float v1 = p[NG];
                const float v2 = p[2 * NG];
                const float v3 = p[3 * NG];

                float o0, o1, o2, o3;
                if (cg == 0) {
                    o0 = fmaf(tanh_half(v0), 4.0f, fmaf((float)s, 8.0f, 4.0f));
                    o1 = fmaf(tanh_half(v1), 4.0f, ybase);
                    o2 = __expf(v2) * aw;
                    o3 = __expf(v3) * ah;
                } else {
                    o0 = fmaf(tanh_half(v0), 0.5f, 0.5f);
                    o1 = fmaf(tanh_half(v1), 0.5f, 0.5f);
                    o2 = fmaf(tanh_half(v2), 0.5f, 0.5f);
                    o3 = fmaf(tanh_half(v3), 0.5f, 0.5f);
                }
                float* t = ob + s * NCH + (cg << 2);
                t[0] = o0; t[1] = o1; t[2] = o2; t[3] = o3;

                // i += 512 => cg += 6, s += 56  (512 = 6*76 + 56)
                cg += 6; s += 56;
                if (s >= NG) { s -= NG; ++cg; }
            }
            // tail channel 84
            if (tid < NG) {
                ob[tid * NCH + 84] = fmaf(tanh_half(ib[84 * NG + tid]), 0.5f, 0.5f);
            }
        }
        __syncthreads();  // compute done: in[buf] consumed, out[buf] complete

        // refill in[buf] with row r+2
        if (r + 2 < NROWS && tid < NCH) {
            const uint64_t g = (uint64_t)(srcb + (size_t)tid * (NGG * 4)
                                               + (size_t)(r + 2) * SEG_B);
            asm volatile(
                "cp.async.bulk.shared::cluster.global.mbarrier::complete_tx::bytes "
                "[%0], [%1], %2, [%3];"
                :: "r"(sbase + (uint32_t)(IN_OFF(buf) * 4) + (uint32_t)(tid * SEG_B)),
                   "l"(g), "r"((uint32_t)SEG_B), "r"(mb)
                : "memory");
        }

        // store out[buf] -> gmem row r
        if (tid == 0) {
            asm volatile("fence.proxy.async.shared::cta;" ::: "memory");
            asm volatile(
                "cp.async.bulk.global.shared::cta.bulk_group [%0], [%1], %2;"
                :: "l"(dst + (size_t)r * ROW_F),
                   "r"(sbase + (uint32_t)(OUT_OFF(buf) * 4)),
                   "r"((uint32_t)ROW_B)
                : "memory");
            asm volatile("cp.async.bulk.commit_group;" ::: "memory");
        }
    }

    // keep CTA alive until the last stores have read smem
    if (tid == 0) {
        asm volatile("cp.async.bulk.wait_group.read 0;" ::: "memory");
    }
}

extern "C" void kernel_launch(void* const* d_in, const int* in_sizes, int n_in,
                              void* d_out, int out_size) {
    const float* x = (const float*)d_in[0];
    float* out = (float*)d_out;

    static bool attr_set = false;
    if (!attr_set) {
        cudaFuncSetAttribute(detection_layer_kernel,
                             cudaFuncAttributeMaxDynamicSharedMemorySize,
                             SMEM_B);
        attr_set = true;
    }

    dim3 grid(NG / NROWS, NA, 16);
    detection_layer_kernel<<<grid, NTHR, SMEM_B>>>(x, out);
}